// round 14
// baseline (speedup 1.0000x reference)
#include <cuda_runtime.h>

#define NN 100000
#define NE 1200000
#define DD 64
#define NBLK 391
#define OFFMASK 0x1FFFFFu
#define GTILE 64
#define GGRID 1563
#define WR2 136
#define ATR 68

typedef unsigned long long ull;

__device__ int      g_count[NN];
__device__ unsigned g_offcnt[NN];
__device__ int      g_rank[NE];
__device__ ull      g_edata[NE];
__device__ float    g_neigh[NN * DD];
__device__ int      g_total;

__device__ __forceinline__ ull pk(float lo, float hi) {
    ull r; asm("mov.b64 %0, {%1, %2};" : "=l"(r) : "f"(lo), "f"(hi)); return r;
}
__device__ __forceinline__ void unpk(float& lo, float& hi, ull v) {
    asm("mov.b64 {%0, %1}, %2;" : "=f"(lo), "=f"(hi) : "l"(v));
}
__device__ __forceinline__ void fma2(ull& d, ull a, ull b) {
    asm("fma.rn.f32x2 %0, %1, %2, %0;" : "+l"(d) : "l"(a), "l"(b));
}
__device__ __forceinline__ ull mul2(ull a, ull b) {
    ull r; asm("mul.rn.f32x2 %0, %1, %2;" : "=l"(r) : "l"(a), "l"(b)); return r;
}

__global__ void __launch_bounds__(256) hist_kernel(const int* __restrict__ dst) {
    unsigned g = blockIdx.x * 256u + threadIdx.x;
    if (g == 0) g_total = 0;
    if (g >= NE / 4) return;
    int4 d = __ldg(reinterpret_cast<const int4*>(dst) + g);
    int4 r;
    r.x = atomicAdd(&g_count[d.x], 1);
    r.y = atomicAdd(&g_count[d.y], 1);
    r.z = atomicAdd(&g_count[d.z], 1);
    r.w = atomicAdd(&g_count[d.w], 1);
    reinterpret_cast<int4*>(g_rank)[g] = r;
}

__global__ void __launch_bounds__(256) offsets_kernel() {
    __shared__ int arr[256];
    __shared__ int sBase;
    int t = threadIdx.x;
    int i = blockIdx.x * 256 + t;
    int c = (i < NN) ? g_count[i] : 0;
    arr[t] = c;
    __syncthreads();
    #pragma unroll
    for (int off = 1; off < 256; off <<= 1) {
        int v = (t >= off) ? arr[t - off] : 0;
        __syncthreads();
        arr[t] += v;
        __syncthreads();
    }
    if (t == 255) sBase = atomicAdd(&g_total, arr[255]);
    __syncthreads();
    if (i < NN) {
        g_offcnt[i] = (unsigned)(sBase + arr[t] - c) | ((unsigned)c << 21);
        g_count[i] = 0;
    }
}

__global__ void __launch_bounds__(256) fill_kernel(
    const int* __restrict__ src, const int* __restrict__ dst,
    const float* __restrict__ ew, const float* __restrict__ em) {
    unsigned g = blockIdx.x * 256u + threadIdx.x;
    if (g >= NE / 4) return;
    int4   s = __ldg(reinterpret_cast<const int4*>(src) + g);
    int4   d = __ldg(reinterpret_cast<const int4*>(dst) + g);
    int4   r = reinterpret_cast<const int4*>(g_rank)[g];
    float4 w = __ldg(reinterpret_cast<const float4*>(ew) + g);
    float4 m = __ldg(reinterpret_cast<const float4*>(em) + g);
    int p0 = (int)(g_offcnt[d.x] & OFFMASK) + r.x;
    int p1 = (int)(g_offcnt[d.y] & OFFMASK) + r.y;
    int p2 = (int)(g_offcnt[d.z] & OFFMASK) + r.z;
    int p3 = (int)(g_offcnt[d.w] & OFFMASK) + r.w;
    g_edata[p0] = ((ull)(unsigned)__float_as_int(w.x * m.x) << 32) | (unsigned)s.x;
    g_edata[p1] = ((ull)(unsigned)__float_as_int(w.y * m.y) << 32) | (unsigned)s.y;
    g_edata[p2] = ((ull)(unsigned)__float_as_int(w.z * m.z) << 32) | (unsigned)s.z;
    g_edata[p3] = ((ull)(unsigned)__float_as_int(w.w * m.w) << 32) | (unsigned)s.w;
}

__global__ void __launch_bounds__(256) gather_kernel(const float* __restrict__ feat) {
    int t = threadIdx.x;
    int nl = t >> 3;
    int l8 = t & 7;
    int node = blockIdx.x * 32 + nl;
    unsigned oc = g_offcnt[node];
    int beg = (int)(oc & OFFMASK);
    int cnt = (int)(oc >> 21);
    ull a0x = 0, a0y = 0, a1x = 0, a1y = 0;
    const ulonglong2* f16 = reinterpret_cast<const ulonglong2*>(feat);
    #pragma unroll 4
    for (int i2 = 0; i2 < cnt; i2++) {
        ull ed = __ldg((const ull*)g_edata + beg + i2);
        int s = (int)(unsigned)(ed & 0xffffffffull);
        float wgt = __int_as_float((int)(ed >> 32));
        ull w2 = pk(wgt, wgt);
        ulonglong2 f0 = __ldg(f16 + (size_t)s * 16 + l8);
        ulonglong2 f1 = __ldg(f16 + (size_t)s * 16 + 8 + l8);
        fma2(a0x, f0.x, w2); fma2(a0y, f0.y, w2);
        fma2(a1x, f1.x, w2); fma2(a1y, f1.y, w2);
    }
    float inv = 1.0f / fmaxf((float)cnt, 1.0f);
    ull iv = pk(inv, inv);
    a0x = mul2(a0x, iv); a0y = mul2(a0y, iv);
    a1x = mul2(a1x, iv); a1y = mul2(a1y, iv);
    float4 o;
    unpk(o.x, o.y, a0x); unpk(o.z, o.w, a0y);
    reinterpret_cast<float4*>(g_neigh)[(size_t)node * 16 + l8] = o;
    unpk(o.x, o.y, a1x); unpk(o.z, o.w, a1y);
    reinterpret_cast<float4*>(g_neigh)[(size_t)node * 16 + 8 + l8] = o;
}

// Dense dual GEMM: node-packed f32x2, zero k-loop splats. 512 threads,
// 64 nodes/block; thread = node pair (2pg, 2pg+1) x 4 cols (j0..j0+3).
// Dup-W floats [8jg, 8jg+8): wL.x->col j0, wL.y->j0+1, wH.x->j0+2, wH.y->j0+3.
__global__ void __launch_bounds__(512) gemm_kernel(
    const float* __restrict__ feat,
    const float* __restrict__ Ws, const float* __restrict__ bs,
    const float* __restrict__ Wn, const float* __restrict__ bn,
    float* __restrict__ out) {
    extern __shared__ float sm[];
    float* sWs2 = sm;                    // 64*136 = 8704 floats (dup W_self)
    float* sWn2 = sm + 8704;             // 8704 (dup W_neigh)
    float* sAT  = sm + 17408;            // 64*68 = 4352 (feat, k-major)
    float* sBT  = sm + 21760;            // 4352 (neigh, k-major) -> 102KB

    int t = threadIdx.x;
    int base = blockIdx.x * GTILE;

    // W pre-splat (coalesced reads; one-time store conflicts acceptable)
    for (int i = t; i < DD * DD; i += 512) {
        int j = i >> 6, k = i & 63;
        float v = Ws[i];
        sWs2[k * WR2 + 2 * j]     = v;
        sWs2[k * WR2 + 2 * j + 1] = v;
        float u = Wn[i];
        sWn2[k * WR2 + 2 * j]     = u;
        sWn2[k * WR2 + 2 * j + 1] = u;
    }
    // A/B k-major transpose (coalesced loads; one-time store conflicts)
    for (int i = t; i < GTILE * 16; i += 512) {
        int n = i >> 4, c = i & 15;
        int node = base + n;
        float4 f = make_float4(0.f, 0.f, 0.f, 0.f);
        float4 h = make_float4(0.f, 0.f, 0.f, 0.f);
        if (node < NN) {
            f = __ldg(reinterpret_cast<const float4*>(feat) + (size_t)node * 16 + c);
            h = reinterpret_cast<const float4*>(g_neigh)[(size_t)node * 16 + c];
        }
        int k0 = 4 * c;
        sAT[(k0 + 0) * ATR + n] = f.x;
        sAT[(k0 + 1) * ATR + n] = f.y;
        sAT[(k0 + 2) * ATR + n] = f.z;
        sAT[(k0 + 3) * ATR + n] = f.w;
        sBT[(k0 + 0) * ATR + n] = h.x;
        sBT[(k0 + 1) * ATR + n] = h.y;
        sBT[(k0 + 2) * ATR + n] = h.z;
        sBT[(k0 + 3) * ATR + n] = h.w;
    }
    __syncthreads();

    int pg = t & 31;       // node pair: local nodes 2pg, 2pg+1 (64 nodes)
    int jg = t >> 5;       // warp-uniform col group 0..15: cols 4jg..4jg+3
    int j0 = 4 * jg;

    ull acc[4];            // acc[c] lanes = (out[n0][j0+c], out[n0+1][j0+c])
    #pragma unroll
    for (int c = 0; c < 4; c++) {
        float bb = __ldg(bs + j0 + c) + __ldg(bn + j0 + c);
        acc[c] = pk(bb, bb);
    }

    const float* pWb = sWs2 + 8 * jg;   // 4 dup-cols = 8 floats
    const float* pUb = sWn2 + 8 * jg;
    const float* pAb = sAT + 2 * pg;
    const float* pBb = sBT + 2 * pg;

    #pragma unroll 8
    for (int k = 0; k < 64; k++) {
        // (136k + 8jg)*4 % 16 == 0 for even jg; use two LDS.64 for safety:
        const ull* wp = reinterpret_cast<const ull*>(pWb + k * WR2);
        const ull* up = reinterpret_cast<const ull*>(pUb + k * WR2);
        ull w0 = wp[0], w1 = wp[1], w2 = wp[2], w3 = wp[3];   // cols j0..j0+3
        ull u0 = up[0], u1 = up[1], u2 = up[2], u3 = up[3];
        ull a = *reinterpret_cast<const ull*>(pAb + k * ATR); // (a_n, a_{n+1})
        ull b = *reinterpret_cast<const ull*>(pBb + k * ATR);
        fma2(acc[0], a, w0); fma2(acc[1], a, w1);
        fma2(acc[2], a, w2); fma2(acc[3], a, w3);
        fma2(acc[0], b, u0); fma2(acc[1], b, u1);
        fma2(acc[2], b, u2); fma2(acc[3], b, u3);
    }

    int n0 = base + 2 * pg;
    float lo[4], hi[4];
    #pragma unroll
    for (int c = 0; c < 4; c++) unpk(lo[c], hi[c], acc[c]);
    if (n0 < NN)
        reinterpret_cast<float4*>(out)[(size_t)n0 * 16 + jg] =
            make_float4(lo[0], lo[1], lo[2], lo[3]);
    if (n0 + 1 < NN)
        reinterpret_cast<float4*>(out)[(size_t)(n0 + 1) * 16 + jg] =
            make_float4(hi[0], hi[1], hi[2], hi[3]);
}

extern "C" void kernel_launch(void* const* d_in, const int* in_sizes, int n_in,
                              void* d_out, int out_size) {
    const float* feat = (const float*)d_in[0];
    const int*   src  = (const int*)d_in[1];
    const int*   dst  = (const int*)d_in[2];
    const float* ew   = (const float*)d_in[3];
    const float* em   = (const float*)d_in[4];
    const float* Ws   = (const float*)d_in[5];
    const float* bs   = (const float*)d_in[6];
    const float* Wn   = (const float*)d_in[7];
    const float* bn   = (const float*)d_in[8];
    float* out = (float*)d_out;

    const int gemm_smem = 26112 * 4;   // 102KB
    cudaFuncSetAttribute(gemm_kernel,
                         cudaFuncAttributeMaxDynamicSharedMemorySize, gemm_smem);

    hist_kernel<<<1172, 256>>>(dst);
    offsets_kernel<<<NBLK, 256>>>();
    fill_kernel<<<1172, 256>>>(src, dst, ew, em);
    gather_kernel<<<3125, 256>>>(feat);
    gemm_kernel<<<GGRID, 512, gemm_smem>>>(feat, Ws, bs, Wn, bn, out);
}

// round 16
// speedup vs baseline: 1.4338x; 1.4338x over previous
#include <cuda_runtime.h>

#define NN 100000
#define NE 1200000
#define DD 64
#define NBLK 391
#define OFFMASK 0x1FFFFFu
#define GTILE 64
#define GGRID 1563          // ceil(NN/64)
#define WR 68               // W smem row stride (floats)
#define AR 33               // A/B smem row stride (ull pairs): 32 pairs + 1 pad

typedef unsigned long long ull;

__device__ int      g_count[NN];
__device__ unsigned g_offcnt[NN];
__device__ int      g_rank[NE];
__device__ ull      g_edata[NE];
__device__ float    g_neigh[NN * DD];
__device__ int      g_total;

__device__ __forceinline__ ull pk(float lo, float hi) {
    ull r; asm("mov.b64 %0, {%1, %2};" : "=l"(r) : "f"(lo), "f"(hi)); return r;
}
__device__ __forceinline__ void unpk(float& lo, float& hi, ull v) {
    asm("mov.b64 {%0, %1}, %2;" : "=f"(lo), "=f"(hi) : "l"(v));
}
__device__ __forceinline__ void fma2(ull& d, ull a, ull b) {
    asm("fma.rn.f32x2 %0, %1, %2, %0;" : "+l"(d) : "l"(a), "l"(b));
}
__device__ __forceinline__ ull mul2(ull a, ull b) {
    ull r; asm("mul.rn.f32x2 %0, %1, %2;" : "=l"(r) : "l"(a), "l"(b)); return r;
}

// Launch 1: histogram + per-edge rank; resets g_total.
__global__ void __launch_bounds__(256) hist_kernel(const int* __restrict__ dst) {
    unsigned g = blockIdx.x * 256u + threadIdx.x;
    if (g == 0) g_total = 0;
    if (g >= NE / 4) return;
    int4 d = __ldg(reinterpret_cast<const int4*>(dst) + g);
    int4 r;
    r.x = atomicAdd(&g_count[d.x], 1);
    r.y = atomicAdd(&g_count[d.y], 1);
    r.z = atomicAdd(&g_count[d.z], 1);
    r.w = atomicAdd(&g_count[d.w], 1);
    reinterpret_cast<int4*>(g_rank)[g] = r;
}

// Launch 2: block-local scan + single atomic base; re-zeros g_count.
__global__ void __launch_bounds__(256) offsets_kernel() {
    __shared__ int arr[256];
    __shared__ int sBase;
    int t = threadIdx.x;
    int i = blockIdx.x * 256 + t;
    int c = (i < NN) ? g_count[i] : 0;
    arr[t] = c;
    __syncthreads();
    #pragma unroll
    for (int off = 1; off < 256; off <<= 1) {
        int v = (t >= off) ? arr[t - off] : 0;
        __syncthreads();
        arr[t] += v;
        __syncthreads();
    }
    if (t == 255) sBase = atomicAdd(&g_total, arr[255]);
    __syncthreads();
    if (i < NN) {
        g_offcnt[i] = (unsigned)(sBase + arr[t] - c) | ((unsigned)c << 21);
        g_count[i] = 0;
    }
}

// Launch 3: atomic-free CSR fill.
__global__ void __launch_bounds__(256) fill_kernel(
    const int* __restrict__ src, const int* __restrict__ dst,
    const float* __restrict__ ew, const float* __restrict__ em) {
    unsigned g = blockIdx.x * 256u + threadIdx.x;
    if (g >= NE / 4) return;
    int4   s = __ldg(reinterpret_cast<const int4*>(src) + g);
    int4   d = __ldg(reinterpret_cast<const int4*>(dst) + g);
    int4   r = reinterpret_cast<const int4*>(g_rank)[g];
    float4 w = __ldg(reinterpret_cast<const float4*>(ew) + g);
    float4 m = __ldg(reinterpret_cast<const float4*>(em) + g);
    int p0 = (int)(g_offcnt[d.x] & OFFMASK) + r.x;
    int p1 = (int)(g_offcnt[d.y] & OFFMASK) + r.y;
    int p2 = (int)(g_offcnt[d.z] & OFFMASK) + r.z;
    int p3 = (int)(g_offcnt[d.w] & OFFMASK) + r.w;
    g_edata[p0] = ((ull)(unsigned)__float_as_int(w.x * m.x) << 32) | (unsigned)s.x;
    g_edata[p1] = ((ull)(unsigned)__float_as_int(w.y * m.y) << 32) | (unsigned)s.y;
    g_edata[p2] = ((ull)(unsigned)__float_as_int(w.z * m.z) << 32) | (unsigned)s.z;
    g_edata[p3] = ((ull)(unsigned)__float_as_int(w.w * m.w) << 32) | (unsigned)s.w;
}

// Launch 4: gather-mean (proven 30us). 8 threads/node, 32 nodes/block.
__global__ void __launch_bounds__(256) gather_kernel(const float* __restrict__ feat) {
    int t = threadIdx.x;
    int nl = t >> 3;
    int l8 = t & 7;
    int node = blockIdx.x * 32 + nl;     // 3125*32 = 100000 exact
    unsigned oc = g_offcnt[node];
    int beg = (int)(oc & OFFMASK);
    int cnt = (int)(oc >> 21);
    ull a0x = 0, a0y = 0, a1x = 0, a1y = 0;
    const ulonglong2* f16 = reinterpret_cast<const ulonglong2*>(feat);
    #pragma unroll 4
    for (int i2 = 0; i2 < cnt; i2++) {
        ull ed = __ldg((const ull*)g_edata + beg + i2);
        int s = (int)(unsigned)(ed & 0xffffffffull);
        float wgt = __int_as_float((int)(ed >> 32));
        ull w2 = pk(wgt, wgt);
        ulonglong2 f0 = __ldg(f16 + (size_t)s * 16 + l8);
        ulonglong2 f1 = __ldg(f16 + (size_t)s * 16 + 8 + l8);
        fma2(a0x, f0.x, w2); fma2(a0y, f0.y, w2);
        fma2(a1x, f1.x, w2); fma2(a1y, f1.y, w2);
    }
    float inv = 1.0f / fmaxf((float)cnt, 1.0f);
    ull iv = pk(inv, inv);
    a0x = mul2(a0x, iv); a0y = mul2(a0y, iv);
    a1x = mul2(a1x, iv); a1y = mul2(a1y, iv);
    float4 o;
    unpk(o.x, o.y, a0x); unpk(o.z, o.w, a0y);
    reinterpret_cast<float4*>(g_neigh)[(size_t)node * 16 + l8] = o;
    unpk(o.x, o.y, a1x); unpk(o.z, o.w, a1y);
    reinterpret_cast<float4*>(g_neigh)[(size_t)node * 16 + 8 + l8] = o;
}

// Launch 5: dense dual GEMM, wavefront-minimized.
// 64 nodes/block (32 pairs), 128 threads: g = t&7 (pair group, pairs g+8m),
// jg = t>>3 (col group, cols 4jg..4jg+3).
// Per k per warp: 2x LDS.128 W/U (4 distinct 16B -> 1 wf each) + 8x LDS.64 A/B
// (8 distinct 8B, 4-way bcast -> 1 wf each) = 10 wf; 8 reg splats; 32 FFMA2.
// Smem: sWs[64*68] + sWn[64*68] + sA[64*33 ull] + sB[64*33 ull] = 68.9KB -> 3 blocks/SM.
__global__ void __launch_bounds__(128) gemm_kernel(
    const float* __restrict__ feat,
    const float* __restrict__ Ws, const float* __restrict__ bs,
    const float* __restrict__ Wn, const float* __restrict__ bn,
    float* __restrict__ out) {
    extern __shared__ float sm[];
    float* sWs = sm;                       // 4352 floats
    float* sWn = sm + 4352;                // 4352 floats
    ull*   sA  = reinterpret_cast<ull*>(sm + 8704);    // 64*33 = 2112 ull
    ull*   sB  = sA + 2112;                            // 2112 ull

    int t = threadIdx.x;
    int base = blockIdx.x * GTILE;

    // W k-major: sW[k*WR + j] = W[j][k] (coalesced reads)
    for (int i = t; i < DD * DD; i += 128) {
        int j = i >> 6, k = i & 63;
        sWs[k * WR + j] = Ws[i];
        sWn[k * WR + j] = Wn[i];
    }
    // A/B pair-packed k-major: sA[k*AR + p] = (feat[base+2p][k], feat[base+2p+1][k]).
    // Write as float halves: float addr = k*(2*AR) + n  (n = 2p + parity).
    {
        float* sAf = reinterpret_cast<float*>(sA);
        float* sBf = reinterpret_cast<float*>(sB);
        for (int i = t; i < GTILE * 16; i += 128) {
            int n = i >> 4, c = i & 15;
            int node = base + n;
            float4 f = make_float4(0.f, 0.f, 0.f, 0.f);
            float4 h = make_float4(0.f, 0.f, 0.f, 0.f);
            if (node < NN) {
                f = __ldg(reinterpret_cast<const float4*>(feat) + (size_t)node * 16 + c);
                h = reinterpret_cast<const float4*>(g_neigh)[(size_t)node * 16 + c];
            }
            int k0 = 4 * c;
            sAf[(k0 + 0) * (2 * AR) + n] = f.x;
            sAf[(k0 + 1) * (2 * AR) + n] = f.y;
            sAf[(k0 + 2) * (2 * AR) + n] = f.z;
            sAf[(k0 + 3) * (2 * AR) + n] = f.w;
            sBf[(k0 + 0) * (2 * AR) + n] = h.x;
            sBf[(k0 + 1) * (2 * AR) + n] = h.y;
            sBf[(k0 + 2) * (2 * AR) + n] = h.z;
            sBf[(k0 + 3) * (2 * AR) + n] = h.w;
        }
    }
    __syncthreads();

    int g  = t & 7;        // pair group: pairs g, g+8, g+16, g+24
    int jg = t >> 3;       // col group 0..15: cols 4jg..4jg+3
    int j0 = 4 * jg;

    ull acc[4][4];         // [m][c]: lanes = (out[2p_m][j0+c], out[2p_m+1][j0+c])
    {
        ull b0 = pk(__ldg(bs + j0 + 0) + __ldg(bn + j0 + 0),
                    __ldg(bs + j0 + 0) + __ldg(bn + j0 + 0));
        ull b1 = pk(__ldg(bs + j0 + 1) + __ldg(bn + j0 + 1),
                    __ldg(bs + j0 + 1) + __ldg(bn + j0 + 1));
        ull b2 = pk(__ldg(bs + j0 + 2) + __ldg(bn + j0 + 2),
                    __ldg(bs + j0 + 2) + __ldg(bn + j0 + 2));
        ull b3 = pk(__ldg(bs + j0 + 3) + __ldg(bn + j0 + 3),
                    __ldg(bs + j0 + 3) + __ldg(bn + j0 + 3));
        #pragma unroll
        for (int m = 0; m < 4; m++) {
            acc[m][0] = b0; acc[m][1] = b1; acc[m][2] = b2; acc[m][3] = b3;
        }
    }

    #pragma unroll 4
    for (int k = 0; k < 64; k++) {
        // (68k + 4jg)*4 bytes % 16 == 0 -> LDS.128, warp-uniform-ish (4 distinct)
        float4 wv = *reinterpret_cast<const float4*>(sWs + k * WR + j0);
        float4 uv = *reinterpret_cast<const float4*>(sWn + k * WR + j0);
        ull w0 = pk(wv.x, wv.x), w1 = pk(wv.y, wv.y);
        ull w2 = pk(wv.z, wv.z), w3 = pk(wv.w, wv.w);
        ull u0 = pk(uv.x, uv.x), u1 = pk(uv.y, uv.y);
        ull u2 = pk(uv.z, uv.z), u3 = pk(uv.w, uv.w);
        const ull* ak = sA + k * AR + g;
        const ull* bk = sB + k * AR + g;
        #pragma unroll
        for (int m = 0; m < 4; m++) {
            ull a = ak[8 * m];       // (a_{2p}, a_{2p+1}) pre-packed
            ull b = bk[8 * m];
            fma2(acc[m][0], a, w0); fma2(acc[m][1], a, w1);
            fma2(acc[m][2], a, w2); fma2(acc[m][3], a, w3);
            fma2(acc[m][0], b, u0); fma2(acc[m][1], b, u1);
            fma2(acc[m][2], b, u2); fma2(acc[m][3], b, u3);
        }
    }

    #pragma unroll
    for (int m = 0; m < 4; m++) {
        int p = g + 8 * m;
        int n0 = base + 2 * p;
        float lo[4], hi[4];
        #pragma unroll
        for (int c = 0; c < 4; c++) unpk(lo[c], hi[c], acc[m][c]);
        if (n0 < NN)
            reinterpret_cast<float4*>(out)[(size_t)n0 * 16 + jg] =
                make_float4(lo[0], lo[1], lo[2], lo[3]);
        if (n0 + 1 < NN)
            reinterpret_cast<float4*>(out)[(size_t)(n0 + 1) * 16 + jg] =
                make_float4(hi[0], hi[1], hi[2], hi[3]);
    }
}

extern "C" void kernel_launch(void* const* d_in, const int* in_sizes, int n_in,
                              void* d_out, int out_size) {
    const float* feat = (const float*)d_in[0];
    const int*   src  = (const int*)d_in[1];
    const int*   dst  = (const int*)d_in[2];
    const float* ew   = (const float*)d_in[3];
    const float* em   = (const float*)d_in[4];
    const float* Ws   = (const float*)d_in[5];
    const float* bs   = (const float*)d_in[6];
    const float* Wn   = (const float*)d_in[7];
    const float* bn   = (const float*)d_in[8];
    float* out = (float*)d_out;

    // smem: 8704 floats (W) + 2*2112 ull = 8704*4 + 4224*8 = 68608 bytes
    const int gemm_smem = 8704 * 4 + 4224 * 8;
    cudaFuncSetAttribute(gemm_kernel,
                         cudaFuncAttributeMaxDynamicSharedMemorySize, gemm_smem);

    hist_kernel<<<1172, 256>>>(dst);
    offsets_kernel<<<NBLK, 256>>>();
    fill_kernel<<<1172, 256>>>(src, dst, ew, em);
    gather_kernel<<<3125, 256>>>(feat);
    gemm_kernel<<<GGRID, 128, gemm_smem>>>(feat, Ws, bs, Wn, bn, out);
}